// round 15
// baseline (speedup 1.0000x reference)
#include <cuda_runtime.h>

// SNNLayer, R15: converged kernel + ONE isolated change — __stcs on the
// output store (evict-first write-once lines, keeping them out of L2's way
// while it services the 1.35GB read stream). Last untested knob; all other
// bytes identical to the converged best (band 185-189us, DRAM 90-92%).
//
//   d_in[0] x              : (256,256,1,32)
//   d_in[1] input_matrix   : (256,256,32,32)
//   d_in[2] layer_weights  : (4,256,256,32,32)
//   out                    : (256,256,1,32)
//
// Evidence-backed design: one cell/warp, 128-thr x 16384 blocks (HW
// work-stealing beats static — R4/R6); lane l=(r=l>>3,c=l&7) -> every
// matrix step is one contiguous 512B LDG.128 warp transaction (R2);
// barrier/smem-free all-SHFL dataflow so stage-2 loads hoist across the
// stage-1 reduction (R3); __ldcs on single-touch streams (R13 A/B: +2%).

#define NCELLS   65536
#define NDIM     32
#define MAT_F4   256            // 1024 floats = 256 float4
#define WARPS_PER_BLOCK 4
#define THREADS  (WARPS_PER_BLOCK * 32)      // 128
#define BLOCKS   (NCELLS / WARPS_PER_BLOCK)  // 16384
#define DECAY    0.8f
#define FULLMASK 0xFFFFFFFFu

__device__ __forceinline__ void reduce_xor(float4& a)
{
#pragma unroll
    for (int m = 8; m <= 16; m <<= 1) {
        a.x += __shfl_xor_sync(FULLMASK, a.x, m);
        a.y += __shfl_xor_sync(FULLMASK, a.y, m);
        a.z += __shfl_xor_sync(FULLMASK, a.z, m);
        a.w += __shfl_xor_sync(FULLMASK, a.w, m);
    }
}

__global__ __launch_bounds__(THREADS, 8)
void snn_layer_kernel(const float* __restrict__ x,
                      const float4* __restrict__ input_matrix,
                      const float4* __restrict__ layer_weights,
                      float4* __restrict__ out)
{
    const int lane = threadIdx.x & 31;
    const int wloc = threadIdx.x >> 5;
    const int r    = lane >> 3;     // row-subgroup 0..3
    const int c    = lane & 7;      // column quad 0..7
    const int cell = blockIdx.x * WARPS_PER_BLOCK + wloc;

    // Lane l holds x[l] for this cell (coalesced 128B per warp).
    const float xreg = x[(size_t)cell * NDIM + lane];

    // ---- Stage 1: act[l] = sum_k x[k] * M[k][l] ----
    const float4* __restrict__ M4 = input_matrix + (size_t)cell * MAT_F4;
    float4 acc = make_float4(0.f, 0.f, 0.f, 0.f);
#pragma unroll
    for (int i = 0; i < 8; ++i) {
        const int k = i * 4 + r;
        const float4 m = __ldcs(&M4[k * 8 + c]);      // 512B contiguous/warp
        const float xv = __shfl_sync(FULLMASK, xreg, k);
        acc.x = fmaf(xv, m.x, acc.x);
        acc.y = fmaf(xv, m.y, acc.y);
        acc.z = fmaf(xv, m.z, acc.z);
        acc.w = fmaf(xv, m.w, acc.w);
    }
    reduce_xor(acc);

    // sel = act[4c + r]  (component r of this lane's reduced quad)
    const float sel = (r == 0) ? acc.x : (r == 1) ? acc.y
                     : (r == 2) ? acc.z : acc.w;

    // Broadcast: av[i] = act[4i + r]  (component r of quad i, lane r*8+i)
    float av[8];
#pragma unroll
    for (int i = 0; i < 8; ++i)
        av[i] = __shfl_sync(FULLMASK, sel, (r << 3) + i);

    // ---- Stage 2: acc2[l] = sum_d sum_n act[n] * W_d[n][l] ----
    float4 acc2 = make_float4(0.f, 0.f, 0.f, 0.f);
    const float4* __restrict__ Wc = layer_weights + (size_t)cell * MAT_F4;
#pragma unroll
    for (int d = 0; d < 4; ++d) {
        const float4* __restrict__ Wd = Wc + (size_t)d * NCELLS * MAT_F4;
#pragma unroll
        for (int i = 0; i < 8; ++i) {
            const int n = i * 4 + r;
            const float4 w = __ldcs(&Wd[n * 8 + c]);  // independent of stage 1
            acc2.x = fmaf(av[i], w.x, acc2.x);
            acc2.y = fmaf(av[i], w.y, acc2.y);
            acc2.z = fmaf(av[i], w.z, acc2.z);
            acc2.w = fmaf(av[i], w.w, acc2.w);
        }
    }
    reduce_xor(acc2);

    if (r == 0) {
        acc2.x *= DECAY; acc2.y *= DECAY; acc2.z *= DECAY; acc2.w *= DECAY;
        __stcs(&out[(size_t)cell * 8 + c], acc2);     // 128B coalesced, evict-first
    }
}

extern "C" void kernel_launch(void* const* d_in, const int* in_sizes, int n_in,
                              void* d_out, int out_size)
{
    const float*  x  = (const float*)d_in[0];
    const float4* im = (const float4*)d_in[1];
    const float4* lw = (const float4*)d_in[2];
    float4* out      = (float4*)d_out;

    snn_layer_kernel<<<BLOCKS, THREADS>>>(x, im, lw, out);
}

// round 16
// speedup vs baseline: 1.0183x; 1.0183x over previous
#include <cuda_runtime.h>

// SNNLayer, FINAL — converged HBM-streaming kernel (15 rounds, complete
// A/B matrix). Best measured 184.8us; stable band 185-190us; DRAM 90-92%
// of 8TB/s (~7.2TB/s); compulsory-traffic floor 170us (1.358GB, single
// touch, AI ~0.5 flop/byte — tensor cores irrelevant by construction).
//
//   d_in[0] x              : (256,256,1,32)
//   d_in[1] input_matrix   : (256,256,32,32)
//   d_in[2] layer_weights  : (4,256,256,32,32)
//   out                    : (256,256,1,32)
//
// Every design element carries an isolated measurement:
//  - One cell per warp, 128-thr blocks, 16384 blocks: HW work-stealing
//    beats static/persistent schedules (R4/R6 regressed ~6%); block scan
//    {64,128,256} -> 128 best (R5/R7).
//  - Lane l = (r=l>>3, c=l&7): lane id maps monotonically to address, so
//    every matrix step is one fully-contiguous 512B LDG.128 warp
//    transaction (R2: -20us vs scalar LDG.32).
//  - Barrier-free / smem-free, all SHFL cross-lane: stage-2 loads hoist
//    across the stage-1 reduction chain (R3: -5us).
//  - __ldcs evict-first on the single-touch read streams (R13 A/B:
//    dropping it costs ~2% DRAM). Plain store (R15: __stcs neutral).
// Plateau invariant under occupancy 33-45%, regs 48-80, prefetch, grid
// structure — residual vs spec is DRAM refresh/turnaround, not SASS.

#define NCELLS   65536
#define NDIM     32
#define MAT_F4   256            // 1024 floats = 256 float4
#define WARPS_PER_BLOCK 4
#define THREADS  (WARPS_PER_BLOCK * 32)      // 128
#define BLOCKS   (NCELLS / WARPS_PER_BLOCK)  // 16384
#define DECAY    0.8f
#define FULLMASK 0xFFFFFFFFu

__device__ __forceinline__ void reduce_xor(float4& a)
{
#pragma unroll
    for (int m = 8; m <= 16; m <<= 1) {
        a.x += __shfl_xor_sync(FULLMASK, a.x, m);
        a.y += __shfl_xor_sync(FULLMASK, a.y, m);
        a.z += __shfl_xor_sync(FULLMASK, a.z, m);
        a.w += __shfl_xor_sync(FULLMASK, a.w, m);
    }
}

__global__ __launch_bounds__(THREADS, 8)
void snn_layer_kernel(const float* __restrict__ x,
                      const float4* __restrict__ input_matrix,
                      const float4* __restrict__ layer_weights,
                      float4* __restrict__ out)
{
    const int lane = threadIdx.x & 31;
    const int wloc = threadIdx.x >> 5;
    const int r    = lane >> 3;     // row-subgroup 0..3
    const int c    = lane & 7;      // column quad 0..7
    const int cell = blockIdx.x * WARPS_PER_BLOCK + wloc;

    // Lane l holds x[l] for this cell (coalesced 128B per warp).
    const float xreg = x[(size_t)cell * NDIM + lane];

    // ---- Stage 1: act[l] = sum_k x[k] * M[k][l] ----
    const float4* __restrict__ M4 = input_matrix + (size_t)cell * MAT_F4;
    float4 acc = make_float4(0.f, 0.f, 0.f, 0.f);
#pragma unroll
    for (int i = 0; i < 8; ++i) {
        const int k = i * 4 + r;
        const float4 m = __ldcs(&M4[k * 8 + c]);      // 512B contiguous/warp
        const float xv = __shfl_sync(FULLMASK, xreg, k);
        acc.x = fmaf(xv, m.x, acc.x);
        acc.y = fmaf(xv, m.y, acc.y);
        acc.z = fmaf(xv, m.z, acc.z);
        acc.w = fmaf(xv, m.w, acc.w);
    }
    reduce_xor(acc);

    // sel = act[4c + r]  (component r of this lane's reduced quad)
    const float sel = (r == 0) ? acc.x : (r == 1) ? acc.y
                     : (r == 2) ? acc.z : acc.w;

    // Broadcast: av[i] = act[4i + r]  (component r of quad i, lane r*8+i)
    float av[8];
#pragma unroll
    for (int i = 0; i < 8; ++i)
        av[i] = __shfl_sync(FULLMASK, sel, (r << 3) + i);

    // ---- Stage 2: acc2[l] = sum_d sum_n act[n] * W_d[n][l] ----
    float4 acc2 = make_float4(0.f, 0.f, 0.f, 0.f);
    const float4* __restrict__ Wc = layer_weights + (size_t)cell * MAT_F4;
#pragma unroll
    for (int d = 0; d < 4; ++d) {
        const float4* __restrict__ Wd = Wc + (size_t)d * NCELLS * MAT_F4;
#pragma unroll
        for (int i = 0; i < 8; ++i) {
            const int n = i * 4 + r;
            const float4 w = __ldcs(&Wd[n * 8 + c]);  // independent of stage 1
            acc2.x = fmaf(av[i], w.x, acc2.x);
            acc2.y = fmaf(av[i], w.y, acc2.y);
            acc2.z = fmaf(av[i], w.z, acc2.z);
            acc2.w = fmaf(av[i], w.w, acc2.w);
        }
    }
    reduce_xor(acc2);

    if (r == 0) {
        acc2.x *= DECAY; acc2.y *= DECAY; acc2.z *= DECAY; acc2.w *= DECAY;
        out[(size_t)cell * 8 + c] = acc2;             // 128B coalesced
    }
}

extern "C" void kernel_launch(void* const* d_in, const int* in_sizes, int n_in,
                              void* d_out, int out_size)
{
    const float*  x  = (const float*)d_in[0];
    const float4* im = (const float4*)d_in[1];
    const float4* lw = (const float4*)d_in[2];
    float4* out      = (float4*)d_out;

    snn_layer_kernel<<<BLOCKS, THREADS>>>(x, im, lw, out);
}